// round 15
// baseline (speedup 1.0000x reference)
#include <cuda_runtime.h>
#include <cuda_bf16.h>

#define NRAYS 4096
#define NTETS 3072
#define NVERT 729
#define NFACE 12288
#define MAXS  128
#define MAXB  896          // boundary-tri capacity (actual count = 768)
#define CAP   128          // per-warp MT candidate list capacity
#define NGRMAX (MAXB / 32) // 28 groups max
#define WPB   28           // warps (=rays) per block
#define TPB   (WPB * 32)   // 896 threads
#define NBLK  ((NRAYS + WPB - 1) / WPB)   // 147 blocks (<=148 SMs, one wave)
#define FPT   ((NFACE + TPB - 1) / TPB)   // 14 fids per thread

// dynamic smem layout (bytes)
#define OFF_TRI   0
#define SZ_TRI    (MAXB * 3 * 16)            // 43008
#define OFF_BOX   (OFF_TRI + SZ_TRI)
#define SZ_BOX    (MAXB * 2 * 16)            // 28672
#define OFF_GBX   (OFF_BOX + SZ_BOX)
#define SZ_GBX    (NGRMAX * 2 * 16)          // 896
#define OFF_LST   (OFF_GBX + SZ_GBX)
#define SZ_LST    (WPB * CAP * 4)            // 14336
#define OFF_VRT   (OFF_LST + SZ_LST)
#define SZ_VRT    ((NVERT * 3 * 4 + 15) & ~15)   // 8752
#define OFF_NB    (OFF_VRT + SZ_VRT)
#define SMEM_TOTAL (OFF_NB + 16)

struct F3 { float x, y, z; };
__device__ __forceinline__ F3 mkf3(float x, float y, float z) { F3 r; r.x = x; r.y = y; r.z = z; return r; }
__device__ __forceinline__ F3 sub3(F3 a, F3 b) { return mkf3(a.x - b.x, a.y - b.y, a.z - b.z); }
__device__ __forceinline__ F3 cross3(F3 a, F3 b) {
    return mkf3(a.y * b.z - a.z * b.y,
                a.z * b.x - a.x * b.z,
                a.x * b.y - a.y * b.x);
}
__device__ __forceinline__ float dot3(F3 a, F3 b) { return a.x * b.x + a.y * b.y + a.z * b.z; }
__device__ __forceinline__ F3 ld3(const float* p) { return mkf3(p[0], p[1], p[2]); }

// safe reciprocal for slab test (conservative vs the 1e-4 AABB padding)
__device__ __forceinline__ float safe_inv(float d) {
    float ad = fabsf(d);
    float dd = (ad < 1e-12f) ? copysignf(1e-12f, d) : d;
    return 1.0f / dd;
}

// ---------------- single fused kernel -----------------------------------------
// 147 blocks x 896 threads (28 warps) -> one wave across all SMs; warp w owns
// ray blockIdx*28+w end-to-end (guarded: last block has 8 live warps).
// Phase 0a: stage verts into smem (coalesced).
// Phase 0b: deterministic compaction of boundary tris in fid order via a block
//   prefix scan (32-slot groups spatially coherent; topo<0 <=> boundary;
//   flattened topo is indexed by face id; first hit from outside a watertight
//   mesh is a boundary face). Face vertex ids derived from tetras:
//   faces[fid] = pick3(tetras[fid>>2], fid&3), rows [ABC],[ABD],[ACD],[BCD].
//   Per-tri padded AABBs built alongside.
// Phase 0c: group AABBs (32 tris/group) via warp shfl-reduction.
// Phase 1 (per warp): slab-test <=28 GROUP boxes in one iteration; for each
//   surviving group, per-tri slab, ballot-compact, dense Moller-Trumbore,
//   shfl-reduce packed (t_bits<<32|fid) == first-occurrence argmin.
//   Cull is conservative -> identical MT set -> bit-identical result.
// Phase 2 (per warp): march -- verbatim R8-R14 speculative stepping.
__global__ void __launch_bounds__(TPB) k_all(const float* __restrict__ verts,
                                             const float* __restrict__ ro,
                                             const float* __restrict__ rd,
                                             const int* __restrict__ tetras,
                                             const int* __restrict__ faces,
                                             const int* __restrict__ topo,
                                             float* __restrict__ out) {
    extern __shared__ unsigned char dynsmem[];
    float4* s_tri = (float4*)(dynsmem + OFF_TRI);
    float4* s_box = (float4*)(dynsmem + OFF_BOX);
    float4* s_gbx = (float4*)(dynsmem + OFF_GBX);
    int*    s_lst = (int*)(dynsmem + OFF_LST);
    float*  s_vrt = (float*)(dynsmem + OFF_VRT);
    int*    s_nb  = (int*)(dynsmem + OFF_NB);

    __shared__ int s_wsum[WPB];

    int tid  = threadIdx.x;
    int lane = tid & 31;
    int wid  = tid >> 5;                 // 0..27 == ray slot in block

    // phase 0a: stage verts coalesced
    for (int i = tid; i < NVERT * 3; i += TPB)
        s_vrt[i] = verts[i];

    // ---------------- phase 0b: deterministic compaction (block scan) --------
    int base_fid = tid * FPT;
    int c = 0;
    int bflag[FPT];
    #pragma unroll
    for (int j = 0; j < FPT; ++j) {
        int fid = base_fid + j;
        bflag[j] = (fid < NFACE) ? (topo[fid] < 0) : 0;
        c += bflag[j];
    }
    // warp inclusive scan of c
    int incl = c;
    #pragma unroll
    for (int off = 1; off < 32; off <<= 1) {
        int n = __shfl_up_sync(0xffffffffu, incl, off);
        if (lane >= off) incl += n;
    }
    if (lane == 31) s_wsum[wid] = incl;
    __syncthreads();
    if (wid == 0) {
        int v = (lane < WPB) ? s_wsum[lane] : 0;
        int vincl = v;
        #pragma unroll
        for (int off = 1; off < 32; off <<= 1) {
            int n = __shfl_up_sync(0xffffffffu, vincl, off);
            if (lane >= off) vincl += n;
        }
        if (lane < WPB) s_wsum[lane] = vincl - v;   // exclusive warp offsets
        if (lane == 31) *s_nb = vincl;              // total boundary count
    }
    __syncthreads();

    const float PAD = 1e-4f;
    {
        int slot = s_wsum[wid] + (incl - c);   // exclusive prefix for this thread
        #pragma unroll
        for (int j = 0; j < FPT; ++j) {
            if (bflag[j]) {
                if (slot < MAXB) {
                    int fid = base_fid + j;
                    int4 tv = ((const int4*)tetras)[fid >> 2];
                    int jj = fid & 3;
                    int v0 = tv.x, v1 = tv.y, v2 = tv.z;        // A,B,C
                    if (jj == 1) { v2 = tv.w; }                 // A,B,D
                    else if (jj == 2) { v1 = tv.z; v2 = tv.w; } // A,C,D
                    else if (jj == 3) { v0 = tv.y; v1 = tv.z; v2 = tv.w; } // B,C,D
                    F3 p0 = ld3(s_vrt + 3 * v0);
                    F3 p1 = ld3(s_vrt + 3 * v1);
                    F3 p2 = ld3(s_vrt + 3 * v2);
                    s_tri[3 * slot + 0] = make_float4(p0.x, p0.y, p0.z, __int_as_float(fid));
                    s_tri[3 * slot + 1] = make_float4(p1.x - p0.x, p1.y - p0.y, p1.z - p0.z, 0.0f);
                    s_tri[3 * slot + 2] = make_float4(p2.x - p0.x, p2.y - p0.y, p2.z - p0.z, 0.0f);
                    float mnx = fminf(p0.x, fminf(p1.x, p2.x)) - PAD;
                    float mny = fminf(p0.y, fminf(p1.y, p2.y)) - PAD;
                    float mnz = fminf(p0.z, fminf(p1.z, p2.z)) - PAD;
                    float mxx = fmaxf(p0.x, fmaxf(p1.x, p2.x)) + PAD;
                    float mxy = fmaxf(p0.y, fmaxf(p1.y, p2.y)) + PAD;
                    float mxz = fmaxf(p0.z, fmaxf(p1.z, p2.z)) + PAD;
                    s_box[2 * slot + 0] = make_float4(mnx, mny, mnz, 0.0f);
                    s_box[2 * slot + 1] = make_float4(mxx, mxy, mxz, 0.0f);
                }
                slot++;
            }
        }
    }
    __syncthreads();

    int nb = *s_nb;
    if (nb > MAXB) nb = MAXB;
    int ngr = (nb + 31) >> 5;            // <= 28

    // ---------------- phase 0c: group AABBs (warp shfl reduction) ------------
    if (wid < ngr) {
        int s = wid * 32 + lane;
        float mnx = 1e30f, mny = 1e30f, mnz = 1e30f;
        float mxx = -1e30f, mxy = -1e30f, mxz = -1e30f;
        if (s < nb) {
            float4 bmn = s_box[2 * s + 0];
            float4 bmx = s_box[2 * s + 1];
            mnx = bmn.x; mny = bmn.y; mnz = bmn.z;
            mxx = bmx.x; mxy = bmx.y; mxz = bmx.z;
        }
        #pragma unroll
        for (int off = 16; off; off >>= 1) {
            mnx = fminf(mnx, __shfl_xor_sync(0xffffffffu, mnx, off));
            mny = fminf(mny, __shfl_xor_sync(0xffffffffu, mny, off));
            mnz = fminf(mnz, __shfl_xor_sync(0xffffffffu, mnz, off));
            mxx = fmaxf(mxx, __shfl_xor_sync(0xffffffffu, mxx, off));
            mxy = fmaxf(mxy, __shfl_xor_sync(0xffffffffu, mxy, off));
            mxz = fmaxf(mxz, __shfl_xor_sync(0xffffffffu, mxz, off));
        }
        if (lane == 0) {
            s_gbx[2 * wid + 0] = make_float4(mnx, mny, mnz, 0.0f);
            s_gbx[2 * wid + 1] = make_float4(mxx, mxy, mxz, 0.0f);
        }
    }
    __syncthreads();

    // ---------------- phases 1+2 (warp = ray, guarded) ------------------------
    int ray = blockIdx.x * WPB + wid;
    if (ray >= NRAYS) return;

    F3 o = ld3(ro + 3 * ray);
    F3 d = ld3(rd + 3 * ray);

    float tmin = 1e10f;
    int   fmin = 0x7fffffff;
    {
        float ivx = safe_inv(d.x), ivy = safe_inv(d.y), ivz = safe_inv(d.z);
        int* wl = s_lst + wid * CAP;
        int cnt = 0;
        unsigned lmask = (1u << lane) - 1u;

        // group-level slab cull (one iteration over <=28 groups)
        bool gacc = false;
        if (lane < ngr) {
            float4 bmn = s_gbx[2 * lane + 0];
            float4 bmx = s_gbx[2 * lane + 1];
            float t0x = (bmn.x - o.x) * ivx, t1x = (bmx.x - o.x) * ivx;
            float t0y = (bmn.y - o.y) * ivy, t1y = (bmx.y - o.y) * ivy;
            float t0z = (bmn.z - o.z) * ivz, t1z = (bmx.z - o.z) * ivz;
            float lo = fmaxf(fminf(t0x, t1x), fmaxf(fminf(t0y, t1y), fminf(t0z, t1z)));
            float hi = fminf(fmaxf(t0x, t1x), fminf(fmaxf(t0y, t1y), fmaxf(t0z, t1z)));
            gacc = (lo <= hi);
        }
        unsigned gmask = __ballot_sync(0xffffffffu, gacc);

        // per-tri slab only within surviving groups
        while (gmask) {
            int g = __ffs(gmask) - 1;
            gmask &= gmask - 1;
            int s = g * 32 + lane;
            bool acc = false;
            if (s < nb) {
                float4 bmn = s_box[2 * s + 0];
                float4 bmx = s_box[2 * s + 1];
                float t0x = (bmn.x - o.x) * ivx, t1x = (bmx.x - o.x) * ivx;
                float t0y = (bmn.y - o.y) * ivy, t1y = (bmx.y - o.y) * ivy;
                float t0z = (bmn.z - o.z) * ivz, t1z = (bmx.z - o.z) * ivz;
                float lo = fmaxf(fminf(t0x, t1x), fmaxf(fminf(t0y, t1y), fminf(t0z, t1z)));
                float hi = fminf(fmaxf(t0x, t1x), fminf(fmaxf(t0y, t1y), fmaxf(t0z, t1z)));
                acc = (lo <= hi);
            }
            unsigned m = __ballot_sync(0xffffffffu, acc);
            if (acc) {
                int pos = cnt + __popc(m & lmask);
                if (pos < CAP) {
                    wl[pos] = s;
                } else {
                    // overflow fallback: immediate MT test (verbatim)
                    float4 q0 = s_tri[3 * s + 0];
                    float4 q1 = s_tri[3 * s + 1];
                    float4 q2 = s_tri[3 * s + 2];
                    F3 p0 = mkf3(q0.x, q0.y, q0.z);
                    F3 e1 = mkf3(q1.x, q1.y, q1.z);
                    F3 e2 = mkf3(q2.x, q2.y, q2.z);
                    int fid = __float_as_int(q0.w);
                    F3 h = cross3(d, e2);
                    float a = dot3(e1, h);
                    bool anz = fabsf(a) > 1e-9f;
                    float f = 1.0f / (anz ? a : 1e-9f);
                    F3 s3 = sub3(o, p0);
                    float u = f * dot3(s3, h);
                    F3 q = cross3(s3, e1);
                    float v = f * dot3(d, q);
                    float tt = f * dot3(e2, q);
                    bool ok = anz && (u >= 0.0f) && (u <= 1.0f) && (v >= 0.0f) &&
                              (u + v <= 1.0f) && (tt > 1e-6f);
                    if (ok && (tt < tmin || (tt == tmin && fid < fmin))) { tmin = tt; fmin = fid; }
                }
            }
            cnt += __popc(m);
        }
        if (cnt > CAP) cnt = CAP;

        // dense MT over compacted candidates (verbatim arithmetic)
        for (int i = lane; i < cnt; i += 32) {
            int s = wl[i];
            float4 q0 = s_tri[3 * s + 0];
            float4 q1 = s_tri[3 * s + 1];
            float4 q2 = s_tri[3 * s + 2];
            F3 p0 = mkf3(q0.x, q0.y, q0.z);
            F3 e1 = mkf3(q1.x, q1.y, q1.z);
            F3 e2 = mkf3(q2.x, q2.y, q2.z);
            int fid = __float_as_int(q0.w);
            F3 h = cross3(d, e2);
            float a = dot3(e1, h);
            bool anz = fabsf(a) > 1e-9f;
            float f = 1.0f / (anz ? a : 1e-9f);
            F3 s3 = sub3(o, p0);
            float u = f * dot3(s3, h);
            F3 q = cross3(s3, e1);
            float v = f * dot3(d, q);
            float tt = f * dot3(e2, q);
            bool ok = anz && (u >= 0.0f) && (u <= 1.0f) && (v >= 0.0f) &&
                      (u + v <= 1.0f) && (tt > 1e-6f);
            if (ok && (tt < tmin || (tt == tmin && fid < fmin))) { tmin = tt; fmin = fid; }
        }
    }

    // warp-wide lexicographic min over packed (t, fid) keys
    unsigned long long key =
        ((unsigned long long)__float_as_uint(tmin) << 32) | (unsigned)fmin;
    #pragma unroll
    for (int off = 16; off; off >>= 1) {
        unsigned long long other = __shfl_xor_sync(0xffffffffu, key, off);
        if (other < key) key = other;
    }

    // ---------------- phase 2: march (warp = ray) -----------------------------
    tmin = __uint_as_float((unsigned)(key >> 32));
    int fidx = (int)(key & 0xffffffffu);

    bool  hit = tmin < 5.0f;
    float t0  = hit ? tmin : 0.0f;
    F3 hp = mkf3(o.x + t0 * d.x, o.y + t0 * d.y, o.z + t0 * d.z);
    int  tet   = hit ? (fidx >> 2) : 0;
    bool alive = hit;

    float* o_ray = out;
    float* o_tet = out + (size_t)NRAYS * MAXS;
    float* o_bar = out + (size_t)2 * NRAYS * MAXS;
    float* o_ts  = out + (size_t)6 * NRAYS * MAXS;
    float* o_te  = o_ts + NRAYS;
    float* o_pos = o_te + NRAYS;

    if (lane == 0) {
        o_ts[ray] = t0;
        o_te[ray] = hit ? (t0 + 0.05f) : 0.0f;
    }

    const float STEPF = (float)(0.05 / 128.0);
    const int   base  = ray * MAXS;          // hoisted output base
    const int   pbase = 3 * base;
    const float fray  = (float)ray;

    // warp-uniform register cache of the current tet (R3's exact arithmetic;
    // vertex data from smem copy -- identical bits)
    F3 ca, ce1, ce2, ce3, cc23;
    float cinv = 0.0f;
    if (alive) {
        int4 tv = ((const int4*)tetras)[tet];
        ca  = ld3(s_vrt + 3 * tv.x);
        F3 b  = ld3(s_vrt + 3 * tv.y);
        F3 c  = ld3(s_vrt + 3 * tv.z);
        F3 dd = ld3(s_vrt + 3 * tv.w);
        ce1 = sub3(b, ca);
        ce2 = sub3(c, ca);
        ce3 = sub3(dd, ca);
        cc23 = cross3(ce2, ce3);
        float det = dot3(ce1, cc23);
        cinv = 1.0f / det;
    }

    int k = 0;
    while (k < MAXS) {
        if (!alive) {
            for (int kk = k + lane; kk < MAXS; kk += 32) {
                int idx = base + kk;
                o_ray[idx] = -1.0f;
                o_tet[idx] = -1.0f;
                ((float4*)o_bar)[idx] = make_float4(0.f, 0.f, 0.f, 0.f);
                o_pos[3 * idx + 0] = 0.0f;
                o_pos[3 * idx + 1] = 0.0f;
                o_pos[3 * idx + 2] = 0.0f;
            }
            break;
        }

        int count = MAXS - k;
        if (count > 32) count = 32;

        // ---- speculative parallel bary for steps k..k+count-1 (tet T) ------
        float w0 = 0.f, w1 = 0.f, w2 = 0.f, w3 = 0.f;
        F3 p = mkf3(0.f, 0.f, 0.f);
        bool inside = false;
        if (lane < count) {
            float tk = (float)(k + lane) * STEPF + 1e-4f;
            p = mkf3(hp.x + tk * d.x, hp.y + tk * d.y, hp.z + tk * d.z);
            F3 r = sub3(p, ca);
            w1 = dot3(r, cc23) * cinv;
            F3 cr3 = cross3(r, ce3);
            w2 = dot3(ce1, cr3) * cinv;
            F3 c2r = cross3(ce2, r);
            w3 = dot3(ce1, c2r) * cinv;
            w0 = 1.0f - (w1 + w2 + w3);
            inside = (w0 >= -1e-6f) && (w1 >= -1e-6f) &&
                     (w2 >= -1e-6f) && (w3 >= -1e-6f);
        }
        unsigned bal = __ballot_sync(0xffffffffu, (lane < count) && !inside);
        int n_ok = (bal == 0u) ? count : (__ffs(bal) - 1);

        // ---- emit the n_ok proven-inside steps (lane-consecutive stores) ---
        if (lane < n_ok) {
            int idx = base + k + lane;
            o_ray[idx] = fray;
            o_tet[idx] = (float)tet;
            ((float4*)o_bar)[idx] = make_float4(w0, w1, w2, w3);
            int pi = pbase + 3 * (k + lane);
            o_pos[pi + 0] = p.x;
            o_pos[pi + 1] = p.y;
            o_pos[pi + 2] = p.z;
        }
        k += n_ok;
        if (bal == 0u) continue;

        // ---- failing step k: all lanes redundantly run the R3 walk ---------
        {
            float tk = (float)k * STEPF + 1e-4f;
            F3 pw = mkf3(hp.x + tk * d.x, hp.y + tk * d.y, hp.z + tk * d.z);
            float v0 = 0.f, v1 = 0.f, v2 = 0.f, v3 = 0.f;
            bool ins = false;
            bool moved_last = false;
            for (int it = 0; it < 3; ++it) {
                F3 r = sub3(pw, ca);
                v1 = dot3(r, cc23) * cinv;
                F3 cr3 = cross3(r, ce3);
                v2 = dot3(ce1, cr3) * cinv;
                F3 c2r = cross3(ce2, r);
                v3 = dot3(ce1, c2r) * cinv;
                v0 = 1.0f - (v1 + v2 + v3);
                ins = (v0 >= -1e-6f) && (v1 >= -1e-6f) &&
                      (v2 >= -1e-6f) && (v3 >= -1e-6f);
                moved_last = false;
                if (ins) break;
                int am = 0; float mv = v0;
                if (v1 < mv) { mv = v1; am = 1; }
                if (v2 < mv) { mv = v2; am = 2; }
                if (v3 < mv) { mv = v3; am = 3; }
                int nb2 = topo[4 * tet + (3 - am)];
                if (nb2 >= 0) {
                    tet = nb2;
                    int4 tv = ((const int4*)tetras)[tet];
                    ca  = ld3(s_vrt + 3 * tv.x);
                    F3 b  = ld3(s_vrt + 3 * tv.y);
                    F3 c  = ld3(s_vrt + 3 * tv.z);
                    F3 dd = ld3(s_vrt + 3 * tv.w);
                    ce1 = sub3(b, ca);
                    ce2 = sub3(c, ca);
                    ce3 = sub3(dd, ca);
                    cc23 = cross3(ce2, ce3);
                    float det = dot3(ce1, cc23);
                    cinv = 1.0f / det;
                    moved_last = true;
                } else { alive = false; break; }
            }
            if (alive && !ins && moved_last) {
                F3 r = sub3(pw, ca);
                v1 = dot3(r, cc23) * cinv;
                F3 cr3 = cross3(r, ce3);
                v2 = dot3(ce1, cr3) * cinv;
                F3 c2r = cross3(ce2, r);
                v3 = dot3(ce1, c2r) * cinv;
                v0 = 1.0f - (v1 + v2 + v3);
                ins = (v0 >= -1e-6f) && (v1 >= -1e-6f) &&
                      (v2 >= -1e-6f) && (v3 >= -1e-6f);
            }
            bool valid = alive && ins;

            if (lane == 0) {
                int idx = base + k;
                if (valid) {
                    o_ray[idx] = fray;
                    o_tet[idx] = (float)tet;
                    ((float4*)o_bar)[idx] = make_float4(v0, v1, v2, v3);
                    int pi = pbase + 3 * k;
                    o_pos[pi + 0] = pw.x;
                    o_pos[pi + 1] = pw.y;
                    o_pos[pi + 2] = pw.z;
                } else {
                    o_ray[idx] = -1.0f;
                    o_tet[idx] = -1.0f;
                    ((float4*)o_bar)[idx] = make_float4(0.f, 0.f, 0.f, 0.f);
                    int pi = pbase + 3 * k;
                    o_pos[pi + 0] = 0.0f;
                    o_pos[pi + 1] = 0.0f;
                    o_pos[pi + 2] = 0.0f;
                }
            }
            k += 1;
        }
    }
}

// ---------------- launch ------------------------------------------------------
extern "C" void kernel_launch(void* const* d_in, const int* in_sizes, int n_in,
                              void* d_out, int out_size) {
    const float* cage   = (const float*)d_in[0];  // (1, 729, 3) f32
    const float* ro     = (const float*)d_in[1];  // (1, 4096, 3) f32
    const float* rd     = (const float*)d_in[2];  // (1, 4096, 3) f32
    const int*   tetras = (const int*)d_in[3];    // (3072, 4) i32
    const int*   faces  = (const int*)d_in[4];    // (3072, 4, 3) i32
    const int*   topo   = (const int*)d_in[5];    // (3072, 4) i32
    float* out = (float*)d_out;

    cudaFuncSetAttribute(k_all, cudaFuncAttributeMaxDynamicSharedMemorySize,
                         SMEM_TOTAL);
    k_all<<<NBLK, TPB, SMEM_TOTAL>>>(cage, ro, rd, tetras, faces, topo, out);
}

// round 16
// speedup vs baseline: 1.1364x; 1.1364x over previous
#include <cuda_runtime.h>
#include <cuda_bf16.h>

#define NRAYS 4096
#define NTETS 3072
#define NVERT 729
#define NFACE 12288
#define MAXS  128
#define MAXB  896          // boundary-tri capacity (actual count = 768)
#define CAP   128          // per-warp MT candidate list capacity
#define NGRMAX (MAXB / 32) // 28 groups max
#define TPB   1024
#define NBLK  (NRAYS / 32) // 128 blocks, one wave
#define FPT   (NFACE / TPB) // 12 fids per thread (3 int4 of topo)

// dynamic smem layout (bytes)
#define OFF_TRI   0
#define SZ_TRI    (MAXB * 3 * 16)            // 43008
#define OFF_BOX   (OFF_TRI + SZ_TRI)
#define SZ_BOX    (MAXB * 2 * 16)            // 28672
#define OFF_GBX   (OFF_BOX + SZ_BOX)
#define SZ_GBX    (NGRMAX * 2 * 16)          // 896
#define OFF_LST   (OFF_GBX + SZ_GBX)
#define SZ_LST    (32 * CAP * 4)             // 16384
#define OFF_VRT   (OFF_LST + SZ_LST)
#define SZ_VRT    ((NVERT * 3 * 4 + 15) & ~15)   // 8752
#define OFF_TET   (OFF_VRT + SZ_VRT)
#define SZ_TET    (NTETS * 16)               // 49152
#define OFF_TPO   (OFF_TET + SZ_TET)
#define SZ_TPO    (NFACE * 4)                // 49152
#define OFF_NB    (OFF_TPO + SZ_TPO)
#define SMEM_TOTAL (OFF_NB + 16)             // ~196KB (< 227KB cap)

struct F3 { float x, y, z; };
__device__ __forceinline__ F3 mkf3(float x, float y, float z) { F3 r; r.x = x; r.y = y; r.z = z; return r; }
__device__ __forceinline__ F3 sub3(F3 a, F3 b) { return mkf3(a.x - b.x, a.y - b.y, a.z - b.z); }
__device__ __forceinline__ F3 cross3(F3 a, F3 b) {
    return mkf3(a.y * b.z - a.z * b.y,
                a.z * b.x - a.x * b.z,
                a.x * b.y - a.y * b.x);
}
__device__ __forceinline__ float dot3(F3 a, F3 b) { return a.x * b.x + a.y * b.y + a.z * b.z; }
__device__ __forceinline__ F3 ld3(const float* p) { return mkf3(p[0], p[1], p[2]); }

// safe reciprocal for slab test (conservative vs the 1e-4 AABB padding)
__device__ __forceinline__ float safe_inv(float d) {
    float ad = fabsf(d);
    float dd = (ad < 1e-12f) ? copysignf(1e-12f, d) : d;
    return 1.0f / dd;
}

// ---------------- single fused kernel -----------------------------------------
// 128 blocks x 1024 threads (32 warps), one wave; warp w owns ray blk*32+w.
// Phase 0a: stage verts + tetras + topo into smem (coalesced); boundary flags
//   derived from the topo int4 registers during staging.
// Phase 0b: deterministic compaction of boundary tris in fid order via block
//   prefix scan (32-slot groups spatially coherent; topo<0 <=> boundary;
//   flattened topo is indexed by face id; first hit from outside a watertight
//   mesh is a boundary face). Face vertex ids derived from tetras:
//   faces[fid] = pick3(tetras[fid>>2], fid&3), rows [ABC],[ABD],[ACD],[BCD].
//   Per-tri padded AABBs built alongside.
// Phase 0c: group AABBs (32 tris/group) via warp shfl-reduction.
// Phase 1 (per warp): slab-test <=28 GROUP boxes in one iteration; surviving
//   groups get per-tri slab, ballot-compact, dense Moller-Trumbore, shfl-min
//   of packed (t_bits<<32|fid) == first-occurrence argmin (conservative cull).
// Phase 2 (per warp): march with speculative 32-wide stepping; walk hops are
//   now all-LDS (topo/tetras/verts staged) -- same bits, ~4x lower latency.
__global__ void __launch_bounds__(TPB) k_all(const float* __restrict__ verts,
                                             const float* __restrict__ ro,
                                             const float* __restrict__ rd,
                                             const int* __restrict__ tetras,
                                             const int* __restrict__ faces,
                                             const int* __restrict__ topo,
                                             float* __restrict__ out) {
    extern __shared__ unsigned char dynsmem[];
    float4* s_tri = (float4*)(dynsmem + OFF_TRI);
    float4* s_box = (float4*)(dynsmem + OFF_BOX);
    float4* s_gbx = (float4*)(dynsmem + OFF_GBX);
    int*    s_lst = (int*)(dynsmem + OFF_LST);
    float*  s_vrt = (float*)(dynsmem + OFF_VRT);
    int4*   s_tet = (int4*)(dynsmem + OFF_TET);
    int*    s_tpo = (int*)(dynsmem + OFF_TPO);
    int*    s_nb  = (int*)(dynsmem + OFF_NB);

    __shared__ int s_wsum[32];

    int tid  = threadIdx.x;
    int lane = tid & 31;
    int wid  = tid >> 5;                 // 0..31 == ray slot in block

    // ---------------- phase 0a: coalesced staging + boundary flags -----------
    for (int i = tid; i < NVERT * 3; i += TPB)
        s_vrt[i] = verts[i];
    for (int i = tid; i < NTETS; i += TPB)
        s_tet[i] = ((const int4*)tetras)[i];

    // topo: thread t stages int4 elems 3t..3t+2 == fids [12t, 12t+12);
    // boundary flags derived from the same registers.
    int c = 0;
    int bflag[FPT];
    {
        const int4* t4 = (const int4*)topo;
        int4* s4 = (int4*)s_tpo;
        #pragma unroll
        for (int j = 0; j < 3; ++j) {
            int4 v = t4[3 * tid + j];
            s4[3 * tid + j] = v;
            bflag[4 * j + 0] = (v.x < 0);
            bflag[4 * j + 1] = (v.y < 0);
            bflag[4 * j + 2] = (v.z < 0);
            bflag[4 * j + 3] = (v.w < 0);
            c += bflag[4 * j + 0] + bflag[4 * j + 1] + bflag[4 * j + 2] + bflag[4 * j + 3];
        }
    }
    int base_fid = tid * FPT;

    // warp inclusive scan of c
    int incl = c;
    #pragma unroll
    for (int off = 1; off < 32; off <<= 1) {
        int n = __shfl_up_sync(0xffffffffu, incl, off);
        if (lane >= off) incl += n;
    }
    if (lane == 31) s_wsum[wid] = incl;
    __syncthreads();
    if (wid == 0) {
        int v = s_wsum[lane];
        int vincl = v;
        #pragma unroll
        for (int off = 1; off < 32; off <<= 1) {
            int n = __shfl_up_sync(0xffffffffu, vincl, off);
            if (lane >= off) vincl += n;
        }
        s_wsum[lane] = vincl - v;        // exclusive warp offsets
        if (lane == 31) *s_nb = vincl;   // total boundary count
    }
    __syncthreads();

    // ---------------- phase 0b: deterministic compaction ---------------------
    const float PAD = 1e-4f;
    {
        int slot = s_wsum[wid] + (incl - c);   // exclusive prefix for this thread
        #pragma unroll
        for (int j = 0; j < FPT; ++j) {
            if (bflag[j]) {
                if (slot < MAXB) {
                    int fid = base_fid + j;
                    int4 tv = s_tet[fid >> 2];
                    int jj = fid & 3;
                    int v0 = tv.x, v1 = tv.y, v2 = tv.z;        // A,B,C
                    if (jj == 1) { v2 = tv.w; }                 // A,B,D
                    else if (jj == 2) { v1 = tv.z; v2 = tv.w; } // A,C,D
                    else if (jj == 3) { v0 = tv.y; v1 = tv.z; v2 = tv.w; } // B,C,D
                    F3 p0 = ld3(s_vrt + 3 * v0);
                    F3 p1 = ld3(s_vrt + 3 * v1);
                    F3 p2 = ld3(s_vrt + 3 * v2);
                    s_tri[3 * slot + 0] = make_float4(p0.x, p0.y, p0.z, __int_as_float(fid));
                    s_tri[3 * slot + 1] = make_float4(p1.x - p0.x, p1.y - p0.y, p1.z - p0.z, 0.0f);
                    s_tri[3 * slot + 2] = make_float4(p2.x - p0.x, p2.y - p0.y, p2.z - p0.z, 0.0f);
                    float mnx = fminf(p0.x, fminf(p1.x, p2.x)) - PAD;
                    float mny = fminf(p0.y, fminf(p1.y, p2.y)) - PAD;
                    float mnz = fminf(p0.z, fminf(p1.z, p2.z)) - PAD;
                    float mxx = fmaxf(p0.x, fmaxf(p1.x, p2.x)) + PAD;
                    float mxy = fmaxf(p0.y, fmaxf(p1.y, p2.y)) + PAD;
                    float mxz = fmaxf(p0.z, fmaxf(p1.z, p2.z)) + PAD;
                    s_box[2 * slot + 0] = make_float4(mnx, mny, mnz, 0.0f);
                    s_box[2 * slot + 1] = make_float4(mxx, mxy, mxz, 0.0f);
                }
                slot++;
            }
        }
    }
    __syncthreads();

    int nb = *s_nb;
    if (nb > MAXB) nb = MAXB;
    int ngr = (nb + 31) >> 5;            // <= 28

    // ---------------- phase 0c: group AABBs (warp shfl reduction) ------------
    if (wid < ngr) {
        int s = wid * 32 + lane;
        float mnx = 1e30f, mny = 1e30f, mnz = 1e30f;
        float mxx = -1e30f, mxy = -1e30f, mxz = -1e30f;
        if (s < nb) {
            float4 bmn = s_box[2 * s + 0];
            float4 bmx = s_box[2 * s + 1];
            mnx = bmn.x; mny = bmn.y; mnz = bmn.z;
            mxx = bmx.x; mxy = bmx.y; mxz = bmx.z;
        }
        #pragma unroll
        for (int off = 16; off; off >>= 1) {
            mnx = fminf(mnx, __shfl_xor_sync(0xffffffffu, mnx, off));
            mny = fminf(mny, __shfl_xor_sync(0xffffffffu, mny, off));
            mnz = fminf(mnz, __shfl_xor_sync(0xffffffffu, mnz, off));
            mxx = fmaxf(mxx, __shfl_xor_sync(0xffffffffu, mxx, off));
            mxy = fmaxf(mxy, __shfl_xor_sync(0xffffffffu, mxy, off));
            mxz = fmaxf(mxz, __shfl_xor_sync(0xffffffffu, mxz, off));
        }
        if (lane == 0) {
            s_gbx[2 * wid + 0] = make_float4(mnx, mny, mnz, 0.0f);
            s_gbx[2 * wid + 1] = make_float4(mxx, mxy, mxz, 0.0f);
        }
    }
    __syncthreads();

    // ---------------- phase 1: intersect (warp = ray) ------------------------
    int ray = blockIdx.x * 32 + wid;
    F3 o = ld3(ro + 3 * ray);
    F3 d = ld3(rd + 3 * ray);

    float tmin = 1e10f;
    int   fmin = 0x7fffffff;
    {
        float ivx = safe_inv(d.x), ivy = safe_inv(d.y), ivz = safe_inv(d.z);
        int* wl = s_lst + wid * CAP;
        int cnt = 0;
        unsigned lmask = (1u << lane) - 1u;

        // group-level slab cull (one iteration over <=28 groups)
        bool gacc = false;
        if (lane < ngr) {
            float4 bmn = s_gbx[2 * lane + 0];
            float4 bmx = s_gbx[2 * lane + 1];
            float t0x = (bmn.x - o.x) * ivx, t1x = (bmx.x - o.x) * ivx;
            float t0y = (bmn.y - o.y) * ivy, t1y = (bmx.y - o.y) * ivy;
            float t0z = (bmn.z - o.z) * ivz, t1z = (bmx.z - o.z) * ivz;
            float lo = fmaxf(fminf(t0x, t1x), fmaxf(fminf(t0y, t1y), fminf(t0z, t1z)));
            float hi = fminf(fmaxf(t0x, t1x), fminf(fmaxf(t0y, t1y), fmaxf(t0z, t1z)));
            gacc = (lo <= hi);
        }
        unsigned gmask = __ballot_sync(0xffffffffu, gacc);

        // per-tri slab only within surviving groups
        while (gmask) {
            int g = __ffs(gmask) - 1;
            gmask &= gmask - 1;
            int s = g * 32 + lane;
            bool acc = false;
            if (s < nb) {
                float4 bmn = s_box[2 * s + 0];
                float4 bmx = s_box[2 * s + 1];
                float t0x = (bmn.x - o.x) * ivx, t1x = (bmx.x - o.x) * ivx;
                float t0y = (bmn.y - o.y) * ivy, t1y = (bmx.y - o.y) * ivy;
                float t0z = (bmn.z - o.z) * ivz, t1z = (bmx.z - o.z) * ivz;
                float lo = fmaxf(fminf(t0x, t1x), fmaxf(fminf(t0y, t1y), fminf(t0z, t1z)));
                float hi = fminf(fmaxf(t0x, t1x), fminf(fmaxf(t0y, t1y), fmaxf(t0z, t1z)));
                acc = (lo <= hi);
            }
            unsigned m = __ballot_sync(0xffffffffu, acc);
            if (acc) {
                int pos = cnt + __popc(m & lmask);
                if (pos < CAP) {
                    wl[pos] = s;
                } else {
                    // overflow fallback: immediate MT test (verbatim)
                    float4 q0 = s_tri[3 * s + 0];
                    float4 q1 = s_tri[3 * s + 1];
                    float4 q2 = s_tri[3 * s + 2];
                    F3 p0 = mkf3(q0.x, q0.y, q0.z);
                    F3 e1 = mkf3(q1.x, q1.y, q1.z);
                    F3 e2 = mkf3(q2.x, q2.y, q2.z);
                    int fid = __float_as_int(q0.w);
                    F3 h = cross3(d, e2);
                    float a = dot3(e1, h);
                    bool anz = fabsf(a) > 1e-9f;
                    float f = 1.0f / (anz ? a : 1e-9f);
                    F3 s3 = sub3(o, p0);
                    float u = f * dot3(s3, h);
                    F3 q = cross3(s3, e1);
                    float v = f * dot3(d, q);
                    float tt = f * dot3(e2, q);
                    bool ok = anz && (u >= 0.0f) && (u <= 1.0f) && (v >= 0.0f) &&
                              (u + v <= 1.0f) && (tt > 1e-6f);
                    if (ok && (tt < tmin || (tt == tmin && fid < fmin))) { tmin = tt; fmin = fid; }
                }
            }
            cnt += __popc(m);
        }
        if (cnt > CAP) cnt = CAP;

        // dense MT over compacted candidates (verbatim arithmetic)
        for (int i = lane; i < cnt; i += 32) {
            int s = wl[i];
            float4 q0 = s_tri[3 * s + 0];
            float4 q1 = s_tri[3 * s + 1];
            float4 q2 = s_tri[3 * s + 2];
            F3 p0 = mkf3(q0.x, q0.y, q0.z);
            F3 e1 = mkf3(q1.x, q1.y, q1.z);
            F3 e2 = mkf3(q2.x, q2.y, q2.z);
            int fid = __float_as_int(q0.w);
            F3 h = cross3(d, e2);
            float a = dot3(e1, h);
            bool anz = fabsf(a) > 1e-9f;
            float f = 1.0f / (anz ? a : 1e-9f);
            F3 s3 = sub3(o, p0);
            float u = f * dot3(s3, h);
            F3 q = cross3(s3, e1);
            float v = f * dot3(d, q);
            float tt = f * dot3(e2, q);
            bool ok = anz && (u >= 0.0f) && (u <= 1.0f) && (v >= 0.0f) &&
                      (u + v <= 1.0f) && (tt > 1e-6f);
            if (ok && (tt < tmin || (tt == tmin && fid < fmin))) { tmin = tt; fmin = fid; }
        }
    }

    // warp-wide lexicographic min over packed (t, fid) keys
    unsigned long long key =
        ((unsigned long long)__float_as_uint(tmin) << 32) | (unsigned)fmin;
    #pragma unroll
    for (int off = 16; off; off >>= 1) {
        unsigned long long other = __shfl_xor_sync(0xffffffffu, key, off);
        if (other < key) key = other;
    }

    // ---------------- phase 2: march (warp = ray) -----------------------------
    tmin = __uint_as_float((unsigned)(key >> 32));
    int fidx = (int)(key & 0xffffffffu);

    bool  hit = tmin < 5.0f;
    float t0  = hit ? tmin : 0.0f;
    F3 hp = mkf3(o.x + t0 * d.x, o.y + t0 * d.y, o.z + t0 * d.z);
    int  tet   = hit ? (fidx >> 2) : 0;
    bool alive = hit;

    float* o_ray = out;
    float* o_tet = out + (size_t)NRAYS * MAXS;
    float* o_bar = out + (size_t)2 * NRAYS * MAXS;
    float* o_ts  = out + (size_t)6 * NRAYS * MAXS;
    float* o_te  = o_ts + NRAYS;
    float* o_pos = o_te + NRAYS;

    if (lane == 0) {
        o_ts[ray] = t0;
        o_te[ray] = hit ? (t0 + 0.05f) : 0.0f;
    }

    const float STEPF = (float)(0.05 / 128.0);
    const int   base  = ray * MAXS;
    const int   pbase = 3 * base;
    const float fray  = (float)ray;

    // warp-uniform register cache of the current tet (R3's exact arithmetic;
    // all mesh data sourced from smem -- identical bits)
    F3 ca, ce1, ce2, ce3, cc23;
    float cinv = 0.0f;
    if (alive) {
        int4 tv = s_tet[tet];
        ca  = ld3(s_vrt + 3 * tv.x);
        F3 b  = ld3(s_vrt + 3 * tv.y);
        F3 c  = ld3(s_vrt + 3 * tv.z);
        F3 dd = ld3(s_vrt + 3 * tv.w);
        ce1 = sub3(b, ca);
        ce2 = sub3(c, ca);
        ce3 = sub3(dd, ca);
        cc23 = cross3(ce2, ce3);
        float det = dot3(ce1, cc23);
        cinv = 1.0f / det;
    }

    int k = 0;
    while (k < MAXS) {
        if (!alive) {
            for (int kk = k + lane; kk < MAXS; kk += 32) {
                int idx = base + kk;
                o_ray[idx] = -1.0f;
                o_tet[idx] = -1.0f;
                ((float4*)o_bar)[idx] = make_float4(0.f, 0.f, 0.f, 0.f);
                o_pos[3 * idx + 0] = 0.0f;
                o_pos[3 * idx + 1] = 0.0f;
                o_pos[3 * idx + 2] = 0.0f;
            }
            break;
        }

        int count = MAXS - k;
        if (count > 32) count = 32;

        // ---- speculative parallel bary for steps k..k+count-1 (tet T) ------
        float w0 = 0.f, w1 = 0.f, w2 = 0.f, w3 = 0.f;
        F3 p = mkf3(0.f, 0.f, 0.f);
        bool inside = false;
        if (lane < count) {
            float tk = (float)(k + lane) * STEPF + 1e-4f;
            p = mkf3(hp.x + tk * d.x, hp.y + tk * d.y, hp.z + tk * d.z);
            F3 r = sub3(p, ca);
            w1 = dot3(r, cc23) * cinv;
            F3 cr3 = cross3(r, ce3);
            w2 = dot3(ce1, cr3) * cinv;
            F3 c2r = cross3(ce2, r);
            w3 = dot3(ce1, c2r) * cinv;
            w0 = 1.0f - (w1 + w2 + w3);
            inside = (w0 >= -1e-6f) && (w1 >= -1e-6f) &&
                     (w2 >= -1e-6f) && (w3 >= -1e-6f);
        }
        unsigned bal = __ballot_sync(0xffffffffu, (lane < count) && !inside);
        int n_ok = (bal == 0u) ? count : (__ffs(bal) - 1);

        // ---- emit the n_ok proven-inside steps (lane-consecutive stores) ---
        if (lane < n_ok) {
            int idx = base + k + lane;
            o_ray[idx] = fray;
            o_tet[idx] = (float)tet;
            ((float4*)o_bar)[idx] = make_float4(w0, w1, w2, w3);
            int pi = pbase + 3 * (k + lane);
            o_pos[pi + 0] = p.x;
            o_pos[pi + 1] = p.y;
            o_pos[pi + 2] = p.z;
        }
        k += n_ok;
        if (bal == 0u) continue;

        // ---- failing step k: all lanes redundantly run the R3 walk ---------
        {
            float tk = (float)k * STEPF + 1e-4f;
            F3 pw = mkf3(hp.x + tk * d.x, hp.y + tk * d.y, hp.z + tk * d.z);
            float v0 = 0.f, v1 = 0.f, v2 = 0.f, v3 = 0.f;
            bool ins = false;
            bool moved_last = false;
            for (int it = 0; it < 3; ++it) {
                F3 r = sub3(pw, ca);
                v1 = dot3(r, cc23) * cinv;
                F3 cr3 = cross3(r, ce3);
                v2 = dot3(ce1, cr3) * cinv;
                F3 c2r = cross3(ce2, r);
                v3 = dot3(ce1, c2r) * cinv;
                v0 = 1.0f - (v1 + v2 + v3);
                ins = (v0 >= -1e-6f) && (v1 >= -1e-6f) &&
                      (v2 >= -1e-6f) && (v3 >= -1e-6f);
                moved_last = false;
                if (ins) break;
                int am = 0; float mv = v0;
                if (v1 < mv) { mv = v1; am = 1; }
                if (v2 < mv) { mv = v2; am = 2; }
                if (v3 < mv) { mv = v3; am = 3; }
                int nb2 = s_tpo[4 * tet + (3 - am)];
                if (nb2 >= 0) {
                    tet = nb2;
                    int4 tv = s_tet[tet];
                    ca  = ld3(s_vrt + 3 * tv.x);
                    F3 b  = ld3(s_vrt + 3 * tv.y);
                    F3 c  = ld3(s_vrt + 3 * tv.z);
                    F3 dd = ld3(s_vrt + 3 * tv.w);
                    ce1 = sub3(b, ca);
                    ce2 = sub3(c, ca);
                    ce3 = sub3(dd, ca);
                    cc23 = cross3(ce2, ce3);
                    float det = dot3(ce1, cc23);
                    cinv = 1.0f / det;
                    moved_last = true;
                } else { alive = false; break; }
            }
            if (alive && !ins && moved_last) {
                F3 r = sub3(pw, ca);
                v1 = dot3(r, cc23) * cinv;
                F3 cr3 = cross3(r, ce3);
                v2 = dot3(ce1, cr3) * cinv;
                F3 c2r = cross3(ce2, r);
                v3 = dot3(ce1, c2r) * cinv;
                v0 = 1.0f - (v1 + v2 + v3);
                ins = (v0 >= -1e-6f) && (v1 >= -1e-6f) &&
                      (v2 >= -1e-6f) && (v3 >= -1e-6f);
            }
            bool valid = alive && ins;

            if (lane == 0) {
                int idx = base + k;
                int pi = pbase + 3 * k;
                if (valid) {
                    o_ray[idx] = fray;
                    o_tet[idx] = (float)tet;
                    ((float4*)o_bar)[idx] = make_float4(v0, v1, v2, v3);
                    o_pos[pi + 0] = pw.x;
                    o_pos[pi + 1] = pw.y;
                    o_pos[pi + 2] = pw.z;
                } else {
                    o_ray[idx] = -1.0f;
                    o_tet[idx] = -1.0f;
                    ((float4*)o_bar)[idx] = make_float4(0.f, 0.f, 0.f, 0.f);
                    o_pos[pi + 0] = 0.0f;
                    o_pos[pi + 1] = 0.0f;
                    o_pos[pi + 2] = 0.0f;
                }
            }
            k += 1;
        }
    }
}

// ---------------- launch ------------------------------------------------------
extern "C" void kernel_launch(void* const* d_in, const int* in_sizes, int n_in,
                              void* d_out, int out_size) {
    const float* cage   = (const float*)d_in[0];  // (1, 729, 3) f32
    const float* ro     = (const float*)d_in[1];  // (1, 4096, 3) f32
    const float* rd     = (const float*)d_in[2];  // (1, 4096, 3) f32
    const int*   tetras = (const int*)d_in[3];    // (3072, 4) i32
    const int*   faces  = (const int*)d_in[4];    // (3072, 4, 3) i32
    const int*   topo   = (const int*)d_in[5];    // (3072, 4) i32
    float* out = (float*)d_out;

    cudaFuncSetAttribute(k_all, cudaFuncAttributeMaxDynamicSharedMemorySize,
                         SMEM_TOTAL);
    k_all<<<NBLK, TPB, SMEM_TOTAL>>>(cage, ro, rd, tetras, faces, topo, out);
}